// round 2
// baseline (speedup 1.0000x reference)
#include <cuda_runtime.h>
#include <math.h>
#include <float.h>

#define QN 16384
#define VN 4096
#define RPB 32               // rows per block
#define NBLK (QN / RPB)      // 512 blocks

// Scratch (allocation-free: __device__ globals per harness rules)
__device__ float g_colsum[VN];
__device__ float g_segmax[VN];
__device__ float g_segsum[VN];
__device__ float g_s[QN];
__device__ float g_t2v;

__global__ void init_kernel() {
    int i = blockIdx.x * blockDim.x + threadIdx.x;
    if (i < VN) {
        g_colsum[i] = 0.f;
        g_segsum[i] = 0.f;
        g_segmax[i] = -FLT_MAX;
    }
    if (i == 0) g_t2v = 0.f;
}

// Fused single pass over the 256MB matrix:
//  - per-row sum(exp) -> row logsumexp -> accumulate (lse - s[q]) for t2v term
//  - per-column sum(exp) into smem accumulator, flushed once per block via atomics
__global__ __launch_bounds__(256) void main_kernel(
    const float* __restrict__ scores, const int* __restrict__ labels) {
    __shared__ float4 colAcc[VN / 4];   // 16 KB column exp-sum accumulator
    __shared__ float warpsum[8];

    int t = threadIdx.x;
    for (int j = t; j < VN / 4; j += 256)
        colAcc[j] = make_float4(0.f, 0.f, 0.f, 0.f);
    __syncthreads();

    float t2v_local = 0.f;
    int row0 = blockIdx.x * RPB;

    for (int r = 0; r < RPB; r++) {
        int row = row0 + r;
        const float4* rp = (const float4*)(scores + (size_t)row * VN);
        float partial = 0.f;
        #pragma unroll
        for (int i = 0; i < 4; i++) {
            int j = t + 256 * i;               // fixed column ownership per thread
            float4 v = __ldg(rp + j);
            float e0 = __expf(v.x), e1 = __expf(v.y);
            float e2 = __expf(v.z), e3 = __expf(v.w);
            partial += (e0 + e1) + (e2 + e3);
            float4 c = colAcc[j];
            c.x += e0; c.y += e1; c.z += e2; c.w += e3;
            colAcc[j] = c;
        }
        // block reduce for row sum(exp)
        #pragma unroll
        for (int o = 16; o > 0; o >>= 1)
            partial += __shfl_down_sync(0xffffffffu, partial, o);
        if ((t & 31) == 0) warpsum[t >> 5] = partial;
        __syncthreads();
        if (t == 0) {
            float sum = warpsum[0];
            #pragma unroll
            for (int w = 1; w < 8; w++) sum += warpsum[w];
            int lab = labels[row] & (VN - 1);  // int32 labels; mask = crash guard
            float s = __ldg(scores + (size_t)row * VN + lab);  // L1/L2 hit (row just read)
            g_s[row] = s;
            t2v_local += __logf(sum) - s;
        }
        __syncthreads();  // protect warpsum reuse next row
    }

    if (t == 0) atomicAdd(&g_t2v, t2v_local);

    // flush column partials (4096 atomics per block; 2M total — negligible)
    for (int j = t; j < VN / 4; j += 256) {
        float4 c = colAcc[j];
        atomicAdd(&g_colsum[4 * j + 0], c.x);
        atomicAdd(&g_colsum[4 * j + 1], c.y);
        atomicAdd(&g_colsum[4 * j + 2], c.z);
        atomicAdd(&g_colsum[4 * j + 3], c.w);
    }
}

// Segment max of s by label (float atomic max via CAS; handles negatives)
__global__ void segmax_kernel(const int* __restrict__ labels) {
    int q = blockIdx.x * blockDim.x + threadIdx.x;
    if (q >= QN) return;
    int lab = labels[q] & (VN - 1);
    float s = g_s[q];
    int* addr = (int*)&g_segmax[lab];
    int old = *((volatile int*)addr);
    while (s > __int_as_float(old)) {
        int assumed = old;
        old = atomicCAS(addr, assumed, __float_as_int(s));
        if (old == assumed) break;
    }
}

__global__ void segsum_kernel(const int* __restrict__ labels) {
    int q = blockIdx.x * blockDim.x + threadIdx.x;
    if (q >= QN) return;
    int lab = labels[q] & (VN - 1);
    atomicAdd(&g_segsum[lab], __expf(g_s[q] - g_segmax[lab]));
}

__global__ void final_kernel(float* __restrict__ out) {
    __shared__ float warpsum[16];
    int t = threadIdx.x;
    float acc = 0.f;
    for (int v = t; v < VN; v += 512) {
        float col_lse = __logf(g_colsum[v]);                 // v2t denominator
        float nom = g_segmax[v] + __logf(g_segsum[v]);       // v2t nominator
        acc += col_lse - nom;
    }
    #pragma unroll
    for (int o = 16; o > 0; o >>= 1)
        acc += __shfl_down_sync(0xffffffffu, acc, o);
    if ((t & 31) == 0) warpsum[t >> 5] = acc;
    __syncthreads();
    if (t == 0) {
        float sum = 0.f;
        #pragma unroll
        for (int w = 0; w < 16; w++) sum += warpsum[w];
        out[0] = g_t2v / (float)QN + sum / (float)VN;
    }
}

extern "C" void kernel_launch(void* const* d_in, const int* in_sizes, int n_in,
                              void* d_out, int out_size) {
    const float* scores = (const float*)d_in[0];
    const int* labels = (const int*)d_in[1];
    float* out = (float*)d_out;

    init_kernel<<<(VN + 255) / 256, 256>>>();
    main_kernel<<<NBLK, 256>>>(scores, labels);
    segmax_kernel<<<(QN + 255) / 256, 256>>>(labels);
    segsum_kernel<<<(QN + 255) / 256, 256>>>(labels);
    final_kernel<<<1, 512>>>(out);
}

// round 3
// speedup vs baseline: 1.0732x; 1.0732x over previous
#include <cuda_runtime.h>
#include <math.h>
#include <float.h>

#define QN 16384
#define VN 4096
#define RPB 32               // rows per block
#define NBLK (QN / RPB)      // 512 blocks

// Scratch (allocation-free). Zero static init is the correct initial state:
// g_segmax_enc uses an order-preserving uint encoding where 0 == -inf.
__device__ float    g_colsum[VN];
__device__ unsigned g_segmax_enc[VN];
__device__ float    g_s[QN];
__device__ float    g_t2v;

__device__ __forceinline__ unsigned enc_f(float x) {
    unsigned u = __float_as_uint(x);
    return (u & 0x80000000u) ? ~u : (u | 0x80000000u);
}
__device__ __forceinline__ float dec_f(unsigned u) {
    return (u & 0x80000000u) ? __uint_as_float(u ^ 0x80000000u)
                             : __uint_as_float(~u);
}

// Single fused pass over the 256MB matrix. No barriers in the hot loop:
//  - row sum(exp): warp shuffle reduce per row, cross-warp combine ONCE at end
//  - column sum(exp): register accumulators (each thread owns 16 fixed columns)
//  - segment max of matched scores: atomicMax on order-preserving uint
__global__ __launch_bounds__(256) void main_kernel(
    const float* __restrict__ scores, const int* __restrict__ labels) {
    __shared__ float rowsum[RPB][8];
    __shared__ float s_t2v;

    int t = threadIdx.x;
    int lane = t & 31, warp = t >> 5;
    if (t == 0) s_t2v = 0.f;

    float4 a0 = make_float4(0.f, 0.f, 0.f, 0.f);
    float4 a1 = a0, a2 = a0, a3 = a0;

    int row0 = blockIdx.x * RPB;
    const float4* base = (const float4*)(scores + (size_t)row0 * VN);

    for (int r = 0; r < RPB; r++) {
        const float4* rp = base + (size_t)r * (VN / 4);
        float4 v0 = rp[t];
        float4 v1 = rp[t + 256];
        float4 v2 = rp[t + 512];
        float4 v3 = rp[t + 768];

        float e00 = __expf(v0.x), e01 = __expf(v0.y), e02 = __expf(v0.z), e03 = __expf(v0.w);
        float e10 = __expf(v1.x), e11 = __expf(v1.y), e12 = __expf(v1.z), e13 = __expf(v1.w);
        float e20 = __expf(v2.x), e21 = __expf(v2.y), e22 = __expf(v2.z), e23 = __expf(v2.w);
        float e30 = __expf(v3.x), e31 = __expf(v3.y), e32 = __expf(v3.z), e33 = __expf(v3.w);

        a0.x += e00; a0.y += e01; a0.z += e02; a0.w += e03;
        a1.x += e10; a1.y += e11; a1.z += e12; a1.w += e13;
        a2.x += e20; a2.y += e21; a2.z += e22; a2.w += e23;
        a3.x += e30; a3.y += e31; a3.z += e32; a3.w += e33;

        float p = ((e00 + e01) + (e02 + e03)) + ((e10 + e11) + (e12 + e13))
                + ((e20 + e21) + (e22 + e23)) + ((e30 + e31) + (e32 + e33));
        #pragma unroll
        for (int o = 16; o > 0; o >>= 1)
            p += __shfl_xor_sync(0xffffffffu, p, o);
        if (lane == 0) rowsum[r][warp] = p;
    }
    __syncthreads();

    if (t < RPB) {
        int row = row0 + t;
        float sum = rowsum[t][0];
        #pragma unroll
        for (int w = 1; w < 8; w++) sum += rowsum[t][w];
        int lab = labels[row] & (VN - 1);
        float s = __ldg(scores + (size_t)row * VN + lab);
        g_s[row] = s;
        atomicMax(&g_segmax_enc[lab], enc_f(s));
        atomicAdd(&s_t2v, __logf(sum) - s);
    }
    __syncthreads();
    if (t == 0) atomicAdd(&g_t2v, s_t2v);

    // flush register column partials (4096 atomics/block; ~2M total)
    atomicAdd(&g_colsum[4 * t + 0], a0.x);
    atomicAdd(&g_colsum[4 * t + 1], a0.y);
    atomicAdd(&g_colsum[4 * t + 2], a0.z);
    atomicAdd(&g_colsum[4 * t + 3], a0.w);
    atomicAdd(&g_colsum[4 * (t + 256) + 0], a1.x);
    atomicAdd(&g_colsum[4 * (t + 256) + 1], a1.y);
    atomicAdd(&g_colsum[4 * (t + 256) + 2], a1.z);
    atomicAdd(&g_colsum[4 * (t + 256) + 3], a1.w);
    atomicAdd(&g_colsum[4 * (t + 512) + 0], a2.x);
    atomicAdd(&g_colsum[4 * (t + 512) + 1], a2.y);
    atomicAdd(&g_colsum[4 * (t + 512) + 2], a2.z);
    atomicAdd(&g_colsum[4 * (t + 512) + 3], a2.w);
    atomicAdd(&g_colsum[4 * (t + 768) + 0], a3.x);
    atomicAdd(&g_colsum[4 * (t + 768) + 1], a3.y);
    atomicAdd(&g_colsum[4 * (t + 768) + 2], a3.z);
    atomicAdd(&g_colsum[4 * (t + 768) + 3], a3.w);
}

// Single block: segmented sum in smem, v-loop, output, then scratch reset
// (restores initial state for the next graph replay).
__global__ __launch_bounds__(1024) void final_kernel(
    const int* __restrict__ labels, float* __restrict__ out) {
    __shared__ float segsum_s[VN];      // 16 KB
    __shared__ float warpsum[32];

    int t = threadIdx.x;
    for (int v = t; v < VN; v += 1024) segsum_s[v] = 0.f;
    __syncthreads();

    for (int q = t; q < QN; q += 1024) {
        int lab = labels[q] & (VN - 1);
        float m = dec_f(g_segmax_enc[lab]);
        atomicAdd(&segsum_s[lab], __expf(g_s[q] - m));
    }
    __syncthreads();

    float acc = 0.f;
    for (int v = t; v < VN; v += 1024) {
        float m = dec_f(g_segmax_enc[v]);
        float nom = m + __logf(segsum_s[v]);      // v2t nominator
        acc += __logf(g_colsum[v]) - nom;         // minus v2t denominator... (denom - nom)
    }
    #pragma unroll
    for (int o = 16; o > 0; o >>= 1)
        acc += __shfl_xor_sync(0xffffffffu, acc, o);
    if ((t & 31) == 0) warpsum[t >> 5] = acc;
    __syncthreads();
    if (t == 0) {
        float sum = 0.f;
        #pragma unroll
        for (int w = 0; w < 32; w++) sum += warpsum[w];
        out[0] = g_t2v / (float)QN + sum / (float)VN;
    }
    __syncthreads();   // all reads of scratch complete before reset
    for (int v = t; v < VN; v += 1024) {
        g_colsum[v] = 0.f;
        g_segmax_enc[v] = 0u;
    }
    if (t == 0) g_t2v = 0.f;
}

extern "C" void kernel_launch(void* const* d_in, const int* in_sizes, int n_in,
                              void* d_out, int out_size) {
    const float* scores = (const float*)d_in[0];
    const int* labels = (const int*)d_in[1];
    float* out = (float*)d_out;

    main_kernel<<<NBLK, 256>>>(scores, labels);
    final_kernel<<<1, 1024>>>(labels, out);
}